// round 4
// baseline (speedup 1.0000x reference)
#include <cuda_runtime.h>
#include <cuda_fp16.h>
#include <cstdint>

// Problem shape (fixed for this dataset entry)
#define M_DIM 8192
#define N_DIM 11008
#define K_DIM 4096
#define KP    (K_DIM / 8)   // 512 packed rows in qweight
#define NZ    (N_DIM / 8)   // 1376 packed cols in qzeros

// GEMM tiling
#define BM 128
#define BN 256
#define BK 32
#define NSTAGE 4
#define KT (K_DIM / BK)     // 128
#define ASTRIDE 40          // BK + 8 halves (80 B/row)
#define BSTRIDE 264         // BN + 8 halves (528 B/row)
#define SA_BYTES (BM * ASTRIDE * 2)              // 10240
#define SB_BYTES (BK * BSTRIDE * 2)              // 16896
#define STAGE_BYTES (SA_BYTES + SB_BYTES)        // 27136
#define MT_TILES (M_DIM / BM)   // 64
#define NT_TILES (N_DIM / BN)   // 43
#define GM 8                     // M-supergroup for L2 reuse

// Scratch (device globals — allocation-free)
__device__ __half g_W[(size_t)K_DIM * N_DIM];   // dequantized W, fp16, [K][N]
__device__ __half g_X[(size_t)M_DIM * K_DIM];   // x fp16, [M][K]

// ---------------------------------------------------------------------------
// Dequant: one thread per qweight word (8 K-values x 1 N-col); stores
// coalesced across threads (adjacent idx -> adjacent n).
// ---------------------------------------------------------------------------
__global__ void dequant_kernel(const int* __restrict__ qw,
                               const float* __restrict__ scales,
                               const int* __restrict__ qz) {
    int idx = blockIdx.x * blockDim.x + threadIdx.x;
    if (idx >= KP * N_DIM) return;
    int n  = idx % N_DIM;
    int kp = idx / N_DIM;
    int g  = kp >> 4;
    unsigned w  = (unsigned)qw[idx];
    unsigned zw = (unsigned)qz[g * NZ + (n >> 3)];
    float z = (float)((zw >> ((n & 7) * 4)) & 0xF);
    float s = scales[g * N_DIM + n];
    size_t base = (size_t)(kp * 8) * N_DIM + n;
#pragma unroll
    for (int j = 0; j < 8; j++) {
        float q = (float)((w >> (4 * j)) & 0xF);
        g_W[base + (size_t)j * N_DIM] = __float2half(s * (q - z));
    }
}

// ---------------------------------------------------------------------------
// x fp32 -> fp16
// ---------------------------------------------------------------------------
__global__ void convert_x_kernel(const float* __restrict__ x) {
    int i = blockIdx.x * blockDim.x + threadIdx.x;
    float4 v = ((const float4*)x)[i];
    __half2* o = (__half2*)g_X;
    o[2 * i]     = __floats2half2_rn(v.x, v.y);
    o[2 * i + 1] = __floats2half2_rn(v.z, v.w);
}

// ---------------------------------------------------------------------------
// PTX helpers (Ampere-class only: target is sm_103 without 'a' features)
// ---------------------------------------------------------------------------
__device__ __forceinline__ void cp_async16(uint32_t dst, const void* src) {
    asm volatile("cp.async.cg.shared.global [%0], [%1], 16;\n" :: "r"(dst), "l"(src));
}
__device__ __forceinline__ void cp_commit() {
    asm volatile("cp.async.commit_group;\n" ::: "memory");
}
__device__ __forceinline__ void cp_wait2() {
    asm volatile("cp.async.wait_group 2;\n" ::: "memory");
}
__device__ __forceinline__ void ldmatrix_x4(uint32_t* r, uint32_t addr) {
    asm volatile("ldmatrix.sync.aligned.m8n8.x4.shared.b16 {%0,%1,%2,%3}, [%4];"
                 : "=r"(r[0]), "=r"(r[1]), "=r"(r[2]), "=r"(r[3]) : "r"(addr));
}
__device__ __forceinline__ void ldmatrix_x4_t(uint32_t* r, uint32_t addr) {
    asm volatile("ldmatrix.sync.aligned.m8n8.x4.trans.shared.b16 {%0,%1,%2,%3}, [%4];"
                 : "=r"(r[0]), "=r"(r[1]), "=r"(r[2]), "=r"(r[3]) : "r"(addr));
}
__device__ __forceinline__ void mma16816(float* c, const uint32_t* a, const uint32_t* b) {
    asm volatile("mma.sync.aligned.m16n8k16.row.col.f32.f16.f16.f32 "
                 "{%0,%1,%2,%3}, {%4,%5,%6,%7}, {%8,%9}, {%0,%1,%2,%3};"
                 : "+f"(c[0]), "+f"(c[1]), "+f"(c[2]), "+f"(c[3])
                 : "r"(a[0]), "r"(a[1]), "r"(a[2]), "r"(a[3]), "r"(b[0]), "r"(b[1]));
}

// ---------------------------------------------------------------------------
// GEMM: out[M,N] = g_X[M,K] * g_W[K,N], fp16 in, fp32 acc
// CTA 128x256x32, 4-stage cp.async, 8 warps as 2(m) x 4(n), warp tile 64x64
// ---------------------------------------------------------------------------
__global__ void __launch_bounds__(256, 1)
gemm_kernel(float* __restrict__ out) {
    extern __shared__ char smem[];
    const uint32_t base = (uint32_t)__cvta_generic_to_shared(smem);

    const int tid  = threadIdx.x;
    const int lane = tid & 31;
    const int warp = tid >> 5;
    const int wm = warp >> 2;   // 0..1
    const int wn = warp & 3;    // 0..3

    // M-supergrouped rasterization for L2 reuse
    int b = blockIdx.x;
    int grp = b / (GM * NT_TILES);
    int rem = b % (GM * NT_TILES);
    int mt = grp * GM + (rem % GM);
    int nt = rem / GM;
    const size_t bm = (size_t)mt * BM;
    const size_t bn = (size_t)nt * BN;

    const __half* gA = g_X + bm * K_DIM;
    const __half* gB = g_W + bn;

    // cp.async assignments
    const int ar0 = tid >> 2,        ak0 = tid & 3;          // A: 2 chunks/thread
    const int ar1 = (tid + 256) >> 2, ak1 = (tid + 256) & 3;

#define LOAD_STAGE(s, kt)                                                       \
    do {                                                                        \
        uint32_t stA = base + (uint32_t)(s) * STAGE_BYTES;                      \
        uint32_t stB = stA + SA_BYTES;                                          \
        const __half* pa = gA + (size_t)(kt) * BK;                              \
        const __half* pb = gB + (size_t)(kt) * BK * N_DIM;                      \
        cp_async16(stA + (ar0 * ASTRIDE + ak0 * 8) * 2,                         \
                   pa + (size_t)ar0 * K_DIM + ak0 * 8);                         \
        cp_async16(stA + (ar1 * ASTRIDE + ak1 * 8) * 2,                         \
                   pa + (size_t)ar1 * K_DIM + ak1 * 8);                         \
        _Pragma("unroll")                                                       \
        for (int i = 0; i < 4; i++) {                                           \
            int c = tid + i * 256;                                              \
            int row = c >> 5, nc = c & 31;                                      \
            cp_async16(stB + (row * BSTRIDE + nc * 8) * 2,                      \
                       pb + (size_t)row * N_DIM + nc * 8);                      \
        }                                                                       \
    } while (0)

    float acc[4][8][4];
#pragma unroll
    for (int mi = 0; mi < 4; mi++)
#pragma unroll
        for (int ni = 0; ni < 8; ni++)
#pragma unroll
            for (int j = 0; j < 4; j++) acc[mi][ni][j] = 0.0f;

    // Prologue: fill 3 stages
    LOAD_STAGE(0, 0); cp_commit();
    LOAD_STAGE(1, 1); cp_commit();
    LOAD_STAGE(2, 2); cp_commit();

    for (int kt = 0; kt < KT; kt++) {
        const int s = kt & 3;
        cp_wait2();               // stage kt resident (FIFO completion)
        __syncthreads();          // also: all warps done reading stage (kt-1)%4

        if (kt + 3 < KT) LOAD_STAGE((kt + 3) & 3, kt + 3);
        cp_commit();

        const uint32_t stA = base + (uint32_t)s * STAGE_BYTES;
        const uint32_t stB = stA + SA_BYTES;

#pragma unroll
        for (int ks = 0; ks < 2; ks++) {
            uint32_t afr[4][4];
#pragma unroll
            for (int mi = 0; mi < 4; mi++) {
                int row = wm * 64 + mi * 16 + (lane & 15);
                int col = ks * 16 + (lane >> 4) * 8;
                ldmatrix_x4(afr[mi], stA + (row * ASTRIDE + col) * 2);
            }
            uint32_t bfr[8][2];
#pragma unroll
            for (int p = 0; p < 4; p++) {
                int row = ks * 16 + (lane & 15);
                int col = wn * 64 + p * 16 + (lane >> 4) * 8;
                uint32_t r[4];
                ldmatrix_x4_t(r, stB + (row * BSTRIDE + col) * 2);
                bfr[2 * p][0] = r[0]; bfr[2 * p][1] = r[1];
                bfr[2 * p + 1][0] = r[2]; bfr[2 * p + 1][1] = r[3];
            }
#pragma unroll
            for (int mi = 0; mi < 4; mi++)
#pragma unroll
                for (int ni = 0; ni < 8; ni++)
                    mma16816(acc[mi][ni], afr[mi], bfr[ni]);
        }
    }
#undef LOAD_STAGE

    // Epilogue: direct fp32 stores (float2 per fragment half)
#pragma unroll
    for (int mi = 0; mi < 4; mi++) {
#pragma unroll
        for (int ni = 0; ni < 8; ni++) {
            size_t r0 = bm + wm * 64 + mi * 16 + (lane >> 2);
            size_t c0 = bn + wn * 64 + ni * 8 + (lane & 3) * 2;
            *(float2*)(out + r0 * N_DIM + c0) =
                make_float2(acc[mi][ni][0], acc[mi][ni][1]);
            *(float2*)(out + (r0 + 8) * N_DIM + c0) =
                make_float2(acc[mi][ni][2], acc[mi][ni][3]);
        }
    }
}

// ---------------------------------------------------------------------------
extern "C" void kernel_launch(void* const* d_in, const int* in_sizes, int n_in,
                              void* d_out, int out_size) {
    (void)in_sizes; (void)n_in; (void)out_size;
    const float* x      = (const float*)d_in[0];
    const int*   qw     = (const int*)d_in[1];
    const float* scales = (const float*)d_in[2];
    const int*   qz     = (const int*)d_in[3];
    float* out = (float*)d_out;

    dequant_kernel<<<(KP * N_DIM + 255) / 256, 256>>>(qw, scales, qz);
    convert_x_kernel<<<(M_DIM * K_DIM / 4) / 256, 256>>>(x);

    const int smem_bytes = NSTAGE * STAGE_BYTES;   // 108544
    cudaFuncSetAttribute(gemm_kernel, cudaFuncAttributeMaxDynamicSharedMemorySize, smem_bytes);
    gemm_kernel<<<MT_TILES * NT_TILES, 256, smem_bytes>>>(out);   // 2752 CTAs
}

// round 5
// speedup vs baseline: 1.2113x; 1.2113x over previous
#include <cuda_runtime.h>
#include <cuda_fp16.h>
#include <cstdint>

// Problem shape (fixed for this dataset entry)
#define M_DIM 8192
#define N_DIM 11008
#define K_DIM 4096
#define KP    (K_DIM / 8)   // 512 packed rows in qweight
#define NZ    (N_DIM / 8)   // 1376 packed cols in qzeros

// GEMM tiling
#define BM 128
#define BN 128
#define BK 64
#define NSTAGE 3
#define KT (K_DIM / BK)     // 64
#define ASTRIDE 72          // BK + 8 halves (144 B/row)
#define BSTRIDE 136         // BN + 8 halves (272 B/row)
#define SA_BYTES (BM * ASTRIDE * 2)          // 18432
#define SB_BYTES (BK * BSTRIDE * 2)          // 17408
#define STAGE_BYTES (SA_BYTES + SB_BYTES)    // 35840
#define MT_TILES (M_DIM / BM)   // 64
#define NT_TILES (N_DIM / BN)   // 86
#define GM 16                    // M-supergroup for L2 reuse

// Scratch (device globals — allocation-free)
__device__ __half g_W[(size_t)K_DIM * N_DIM];   // dequantized W, fp16, [K][N]
__device__ __half g_X[(size_t)M_DIM * K_DIM];   // x fp16, [M][K]

// ---------------------------------------------------------------------------
// Dequant: one thread per qweight word (8 K-values x 1 N-col)
// ---------------------------------------------------------------------------
__global__ void dequant_kernel(const int* __restrict__ qw,
                               const float* __restrict__ scales,
                               const int* __restrict__ qz) {
    int idx = blockIdx.x * blockDim.x + threadIdx.x;
    if (idx >= KP * N_DIM) return;
    int n  = idx % N_DIM;
    int kp = idx / N_DIM;
    int g  = kp >> 4;
    unsigned w  = (unsigned)qw[idx];
    unsigned zw = (unsigned)qz[g * NZ + (n >> 3)];
    float z = (float)((zw >> ((n & 7) * 4)) & 0xF);
    float s = scales[g * N_DIM + n];
    size_t base = (size_t)(kp * 8) * N_DIM + n;
#pragma unroll
    for (int j = 0; j < 8; j++) {
        float q = (float)((w >> (4 * j)) & 0xF);
        g_W[base + (size_t)j * N_DIM] = __float2half(s * (q - z));
    }
}

// ---------------------------------------------------------------------------
// x fp32 -> fp16
// ---------------------------------------------------------------------------
__global__ void convert_x_kernel(const float* __restrict__ x) {
    int i = blockIdx.x * blockDim.x + threadIdx.x;
    float4 v = ((const float4*)x)[i];
    __half2* o = (__half2*)g_X;
    o[2 * i]     = __floats2half2_rn(v.x, v.y);
    o[2 * i + 1] = __floats2half2_rn(v.z, v.w);
}

// ---------------------------------------------------------------------------
// PTX helpers (Ampere-class only: target is sm_103 without 'a' features)
// ---------------------------------------------------------------------------
__device__ __forceinline__ void cp_async16(uint32_t dst, const void* src) {
    asm volatile("cp.async.cg.shared.global [%0], [%1], 16;\n" :: "r"(dst), "l"(src));
}
__device__ __forceinline__ void cp_commit() {
    asm volatile("cp.async.commit_group;\n" ::: "memory");
}
__device__ __forceinline__ void cp_wait1() {
    asm volatile("cp.async.wait_group 1;\n" ::: "memory");
}
__device__ __forceinline__ void ldmatrix_x4(uint32_t* r, uint32_t addr) {
    asm volatile("ldmatrix.sync.aligned.m8n8.x4.shared.b16 {%0,%1,%2,%3}, [%4];"
                 : "=r"(r[0]), "=r"(r[1]), "=r"(r[2]), "=r"(r[3]) : "r"(addr));
}
__device__ __forceinline__ void ldmatrix_x4_t(uint32_t* r, uint32_t addr) {
    asm volatile("ldmatrix.sync.aligned.m8n8.x4.trans.shared.b16 {%0,%1,%2,%3}, [%4];"
                 : "=r"(r[0]), "=r"(r[1]), "=r"(r[2]), "=r"(r[3]) : "r"(addr));
}
__device__ __forceinline__ void mma16816(float* c, const uint32_t* a, const uint32_t* b) {
    asm volatile("mma.sync.aligned.m16n8k16.row.col.f32.f16.f16.f32 "
                 "{%0,%1,%2,%3}, {%4,%5,%6,%7}, {%8,%9}, {%0,%1,%2,%3};"
                 : "+f"(c[0]), "+f"(c[1]), "+f"(c[2]), "+f"(c[3])
                 : "r"(a[0]), "r"(a[1]), "r"(a[2]), "r"(a[3]), "r"(b[0]), "r"(b[1]));
}

// ---------------------------------------------------------------------------
// GEMM: out[M,N] = g_X[M,K] * g_W[K,N], fp16 in, fp32 acc
// CTA 128x128x64, 3-stage cp.async, 8 warps as 4(m) x 2(n), warp tile 32x64
// 2 CTAs/SM (smem 105KB total for both, regs capped at 128)
// ---------------------------------------------------------------------------
__global__ void __launch_bounds__(256, 2)
gemm_kernel(float* __restrict__ out) {
    extern __shared__ char smem[];
    const uint32_t base = (uint32_t)__cvta_generic_to_shared(smem);

    const int tid  = threadIdx.x;
    const int lane = tid & 31;
    const int warp = tid >> 5;
    const int wm = warp >> 1;   // 0..3
    const int wn = warp & 1;    // 0..1

    // M-supergrouped rasterization for L2 reuse
    int b = blockIdx.x;
    int grp = b / (GM * NT_TILES);
    int rem = b % (GM * NT_TILES);
    int mt = grp * GM + (rem % GM);
    int nt = rem / GM;
    const size_t bm = (size_t)mt * BM;
    const size_t bn = (size_t)nt * BN;

    const __half* gA = g_X + bm * K_DIM;
    const __half* gB = g_W + bn;

#define LOAD_STAGE(s, kt)                                                       \
    do {                                                                        \
        uint32_t stA = base + (uint32_t)(s) * STAGE_BYTES;                      \
        uint32_t stB = stA + SA_BYTES;                                          \
        const __half* pa = gA + (size_t)(kt) * BK;                              \
        const __half* pb = gB + (size_t)(kt) * BK * N_DIM;                      \
        _Pragma("unroll")                                                       \
        for (int i = 0; i < 4; i++) {                                           \
            int c = tid + i * 256;                                              \
            int row = c >> 3, col = c & 7;     /* A: 8 chunks per 64-half row */\
            cp_async16(stA + (row * ASTRIDE + col * 8) * 2,                     \
                       pa + (size_t)row * K_DIM + col * 8);                     \
        }                                                                       \
        _Pragma("unroll")                                                       \
        for (int i = 0; i < 4; i++) {                                           \
            int c = tid + i * 256;                                              \
            int row = c >> 4, col = c & 15;    /* B: 16 chunks per 128-half row */\
            cp_async16(stB + (row * BSTRIDE + col * 8) * 2,                     \
                       pb + (size_t)row * N_DIM + col * 8);                     \
        }                                                                       \
    } while (0)

    float acc[2][8][4];
#pragma unroll
    for (int mi = 0; mi < 2; mi++)
#pragma unroll
        for (int ni = 0; ni < 8; ni++)
#pragma unroll
            for (int j = 0; j < 4; j++) acc[mi][ni][j] = 0.0f;

    // Prologue: fill 2 stages
    LOAD_STAGE(0, 0); cp_commit();
    LOAD_STAGE(1, 1); cp_commit();

    for (int kt = 0; kt < KT; kt++) {
        const int s = kt % NSTAGE;
        cp_wait1();               // stage kt resident (FIFO; kt+1 may be pending)
        __syncthreads();          // all warps done reading slot (kt-1)%3 == slot kt+2

        if (kt + 2 < KT) { LOAD_STAGE((kt + 2) % NSTAGE, kt + 2); cp_commit(); }

        const uint32_t stA = base + (uint32_t)s * STAGE_BYTES;
        const uint32_t stB = stA + SA_BYTES;

#pragma unroll
        for (int ks = 0; ks < 4; ks++) {
            uint32_t afr[2][4];
#pragma unroll
            for (int mi = 0; mi < 2; mi++) {
                int row = wm * 32 + mi * 16 + (lane & 15);
                int col = ks * 16 + (lane >> 4) * 8;
                ldmatrix_x4(afr[mi], stA + (row * ASTRIDE + col) * 2);
            }
            uint32_t bfr[8][2];
#pragma unroll
            for (int p = 0; p < 4; p++) {
                int row = ks * 16 + (lane & 15);
                int col = wn * 64 + p * 16 + (lane >> 4) * 8;
                uint32_t r[4];
                ldmatrix_x4_t(r, stB + (row * BSTRIDE + col) * 2);
                bfr[2 * p][0] = r[0]; bfr[2 * p][1] = r[1];
                bfr[2 * p + 1][0] = r[2]; bfr[2 * p + 1][1] = r[3];
            }
#pragma unroll
            for (int mi = 0; mi < 2; mi++)
#pragma unroll
                for (int ni = 0; ni < 8; ni++)
                    mma16816(acc[mi][ni], afr[mi], bfr[ni]);
        }
    }
#undef LOAD_STAGE

    // Epilogue: direct fp32 stores (float2 per fragment half)
#pragma unroll
    for (int mi = 0; mi < 2; mi++) {
#pragma unroll
        for (int ni = 0; ni < 8; ni++) {
            size_t r0 = bm + wm * 32 + mi * 16 + (lane >> 2);
            size_t c0 = bn + wn * 64 + ni * 8 + (lane & 3) * 2;
            *(float2*)(out + r0 * N_DIM + c0) =
                make_float2(acc[mi][ni][0], acc[mi][ni][1]);
            *(float2*)(out + (r0 + 8) * N_DIM + c0) =
                make_float2(acc[mi][ni][2], acc[mi][ni][3]);
        }
    }
}

// ---------------------------------------------------------------------------
extern "C" void kernel_launch(void* const* d_in, const int* in_sizes, int n_in,
                              void* d_out, int out_size) {
    (void)in_sizes; (void)n_in; (void)out_size;
    const float* x      = (const float*)d_in[0];
    const int*   qw     = (const int*)d_in[1];
    const float* scales = (const float*)d_in[2];
    const int*   qz     = (const int*)d_in[3];
    float* out = (float*)d_out;

    dequant_kernel<<<(KP * N_DIM + 255) / 256, 256>>>(qw, scales, qz);
    convert_x_kernel<<<(M_DIM * K_DIM / 4) / 256, 256>>>(x);

    const int smem_bytes = NSTAGE * STAGE_BYTES;   // 107520
    cudaFuncSetAttribute(gemm_kernel, cudaFuncAttributeMaxDynamicSharedMemorySize, smem_bytes);
    gemm_kernel<<<MT_TILES * NT_TILES, 256, smem_bytes>>>(out);   // 5504 CTAs
}